// round 13
// baseline (speedup 1.0000x reference)
#include <cuda_runtime.h>
#include <cuda_fp16.h>
#include <cstdint>

#define B_SZ 65536
#define H 256

// ---------------- static scratch (no allocation) ----------------------------
// Wz layout: row r = jhi*64 + g*16 + jlo  (j = jhi*16+jlo, g in 0..3), 512 k
// Ws layout: row r = jhi*32 + g*16 + jlo  (g in 0..1), 512 k
__device__ __half g_Wz[1024 * 512];
__device__ __half g_Ws[512 * 512];
__device__ __half g_Ax[(size_t)B_SZ * 256];
__device__ __half g_Ah[(size_t)B_SZ * 256];
__device__ __half g_As[(size_t)B_SZ * 256];
__device__ float  g_biasz[1024];   // [g*256 + j]
__device__ float  g_biass[512];    // [g*256 + j]

// ---------------- prepass kernels (bias merged into reorder) -----------------
__global__ void reorder_kernel(const float* __restrict__ w_ih,
                               const float* __restrict__ w_hh,
                               const float* __restrict__ w_sh,
                               const float* __restrict__ bi,
                               const float* __restrict__ bh,
                               const float* __restrict__ bs) {
    int tid = blockIdx.x * blockDim.x + threadIdx.x;
    if (tid < 1024 * 512) {
        int r = tid >> 9, k = tid & 511;
        int jhi = r >> 6, g = (r >> 4) & 3, jlo = r & 15;
        int j = jhi * 16 + jlo;
        float v = (k < 256) ? w_ih[(g * 256 + j) * 256 + k]
                            : w_hh[(g * 256 + j) * 256 + (k - 256)];
        g_Wz[tid] = __float2half_rn(v);
    } else if (tid < 786432) {
        int t2 = tid - 524288;
        int r = t2 >> 9, k = t2 & 511;
        int jhi = r >> 5, g = (r >> 4) & 1, jlo = r & 15;
        int j = jhi * 16 + jlo;
        float v = (k < 256) ? w_ih[((4 + g) * 256 + j) * 256 + k]
                            : w_sh[(g * 256 + j) * 256 + (k - 256)];
        g_Ws[t2] = __float2half_rn(v);
    } else if (tid < 787456) {
        int t = tid - 786432;
        g_biasz[t] = bi[t] + bh[t];
    } else if (tid < 787968) {
        int t = tid - 787456;
        g_biass[t] = bi[1024 + t] + bs[t];
    }
}

static __device__ __forceinline__ uint32_t h2u(__half2 h) {
    union { __half2 h; uint32_t u; } c; c.h = h; return c.u;
}

__global__ void aconv_kernel(const float* __restrict__ x,
                             const float* __restrict__ hm,
                             const float* __restrict__ s_all,
                             const int* __restrict__ idxp) {
    size_t gid = (size_t)blockIdx.x * blockDim.x + threadIdx.x;
    size_t off = gid * 8;
    const float* src; __half* dst;
    if (blockIdx.y == 0)      { src = x;  dst = g_Ax; }
    else if (blockIdx.y == 1) { src = hm; dst = g_Ah; }
    else { src = s_all + (size_t)(*idxp) * ((size_t)B_SZ * 256); dst = g_As; }
    float4 v0 = *(const float4*)(src + off);
    float4 v1 = *(const float4*)(src + off + 4);
    uint4 p;
    p.x = h2u(__floats2half2_rn(v0.x, v0.y));
    p.y = h2u(__floats2half2_rn(v0.z, v0.w));
    p.z = h2u(__floats2half2_rn(v1.x, v1.y));
    p.w = h2u(__floats2half2_rn(v1.z, v1.w));
    *(uint4*)(dst + off) = p;
}

// ---------------- PTX helpers ------------------------------------------------
static __device__ __forceinline__ uint32_t smem_u32(const void* p) {
    return (uint32_t)__cvta_generic_to_shared(p);
}
static __device__ __forceinline__ void cp16(uint32_t dst, const void* src) {
    asm volatile("cp.async.cg.shared.global [%0], [%1], 16;"
                 :: "r"(dst), "l"(src) : "memory");
}
static __device__ __forceinline__ void cp_commit() {
    asm volatile("cp.async.commit_group;" ::: "memory");
}
#define CP_WAIT(NSTR) asm volatile("cp.async.wait_group " NSTR ";" ::: "memory")

static __device__ __forceinline__ void ldmatrix_x4(uint32_t* r, uint32_t addr) {
    asm volatile("ldmatrix.sync.aligned.m8n8.x4.shared.b16 {%0,%1,%2,%3}, [%4];"
                 : "=r"(r[0]), "=r"(r[1]), "=r"(r[2]), "=r"(r[3]) : "r"(addr));
}
static __device__ __forceinline__ void mma16816(float* c, const uint32_t* a,
                                                uint32_t b0, uint32_t b1) {
    asm volatile("mma.sync.aligned.m16n8k16.row.col.f32.f16.f16.f32 "
                 "{%0,%1,%2,%3}, {%4,%5,%6,%7}, {%8,%9}, {%0,%1,%2,%3};"
                 : "+f"(c[0]), "+f"(c[1]), "+f"(c[2]), "+f"(c[3])
                 : "r"(a[0]), "r"(a[1]), "r"(a[2]), "r"(a[3]), "r"(b0), "r"(b1));
}
static __device__ __forceinline__ uint32_t swz128(uint32_t o) {
    return o ^ ((o >> 3) & 0x70);
}
static __device__ __forceinline__ float fast_tanh(float x) {
    float r; asm("tanh.approx.f32 %0, %1;" : "=f"(r) : "f"(x)); return r;
}
static __device__ __forceinline__ float fast_sig(float x) {
    return fmaf(0.5f, fast_tanh(0.5f * x), 0.5f);
}

// SMEM map per CTA (128B rows + swz128 everywhere):
//  A1 stages:  s*8192          (64 rows x 128B)
//  A2 stages:  16384 + s*8192
//  Wz stages:  32768 + p*32768 (256 rows x 128B) -- parity double-buffered
//  Ws:         98304           (128 rows x 128B) -- single, just-in-time
#define SM_A1(s) ((s) * 8192)
#define SM_A2(s) (16384 + (s) * 8192)
#define SM_WZ(p) (32768 + (p) * 32768)
#define SM_WS    98304
#define SMEM_TOTAL 114688

// ---------------- fused HMMA GEMM + LSTM epilogue ---------------------------
__global__ void __launch_bounds__(256, 2)
lstm_hmma_kernel(const float* __restrict__ c_in,
                 const float* __restrict__ mask,
                 float* __restrict__ out)
{
    extern __shared__ char smem[];
    const int tid  = threadIdx.x;
    const int lane = tid & 31;
    const int wid  = tid >> 5;
    const int warp_m = wid & 1;           // 2 warps x 32 rows
    const int warp_n = wid >> 1;          // 4 warps x 16 j
    const int j0 = blockIdx.x * 64;
    const int m0 = blockIdx.y * 64;

    float accz[2][8][4], accs[2][4][4];
    #pragma unroll
    for (int mt = 0; mt < 2; mt++) {
        #pragma unroll
        for (int f = 0; f < 8; f++)
            #pragma unroll
            for (int q = 0; q < 4; q++) accz[mt][f][q] = 0.f;
        #pragma unroll
        for (int f = 0; f < 4; f++)
            #pragma unroll
            for (int q = 0; q < 4; q++) accs[mt][f][q] = 0.f;
    }

    // ---- fragment addressing (identical to the proven R6 round) ------------
    const uint32_t rowA = warp_m * 32 + (lane & 15);
    const uint32_t axA  = ((lane & 7) * 16) ^ ((lane >> 4) * 16);
    const uint32_t offA = rowA * 128;
    const uint32_t rowB0 = ((lane >> 4) & 1) * 8 + (lane & 7);
    const uint32_t axB   = ((lane & 7) * 16) ^ (((lane >> 3) & 1) * 16);
    const uint32_t offBz = (warp_n * 64 + rowB0) * 128;
    const uint32_t offBs = (warp_n * 32 + rowB0) * 128;
    const uint32_t sbase = smem_u32(smem);

    auto issueA = [&](int kb) {
        const uint32_t sg = sbase + SM_A1(kb & 1);
        const bool ph1 = (kb < 4);
        const int c0 = (ph1 ? kb : kb - 4) * 64;
        const __half* a1g = ph1 ? g_Ax : g_Ah;
        #pragma unroll
        for (int i = 0; i < 2; i++) {
            int id = tid + i * 256, r = id >> 3, cc = id & 7;
            cp16(sg + swz128(r * 128 + cc * 16),
                 a1g + (size_t)(m0 + r) * 256 + c0 + cc * 8);
        }
        if (!ph1) {
            const uint32_t sg2 = sbase + SM_A2(kb & 1);
            #pragma unroll
            for (int i = 0; i < 2; i++) {
                int id = tid + i * 256, r = id >> 3, cc = id & 7;
                cp16(sg2 + swz128(r * 128 + cc * 16),
                     g_As + (size_t)(m0 + r) * 256 + c0 + cc * 8);
            }
        }
        cp_commit();
    };

    auto issueWz = [&](int kb) {
        const uint32_t wb = sbase + SM_WZ(kb & 1);
        #pragma unroll
        for (int i = 0; i < 8; i++) {
            int id = tid + i * 256, r = id >> 3, cc = id & 7;
            cp16(wb + swz128(r * 128 + cc * 16),
                 g_Wz + (size_t)(j0 * 4 + r) * 512 + kb * 64 + cc * 8);
        }
        cp_commit();
    };

    auto issueWs = [&](int kb) {
        #pragma unroll
        for (int i = 0; i < 4; i++) {
            int id = tid + i * 256, r = id >> 3, cc = id & 7;
            cp16(sbase + SM_WS + swz128(r * 128 + cc * 16),
                 g_Ws + (size_t)(j0 * 2 + r) * 512 + kb * 64 + cc * 8);
        }
        cp_commit();
    };

    // ---- R6 compute body, verbatim (interleaved z+s per k-step) -------------
    auto computeChunk = [&](int kb) {
        const bool ph2 = (kb >= 4);
        const uint32_t A1b = sbase + SM_A1(kb & 1) + offA;
        const uint32_t A2b = sbase + SM_A2(kb & 1) + offA;
        const uint32_t Wzb = sbase + SM_WZ(kb & 1) + offBz;
        const uint32_t Wsb = sbase + SM_WS + offBs;
        #pragma unroll
        for (int kk4 = 0; kk4 < 4; kk4++) {
            const uint32_t KK2 = kk4 * 32;
            uint32_t az[2][4];
            ldmatrix_x4(az[0], A1b + (KK2 ^ axA));
            ldmatrix_x4(az[1], A1b + 2048 + (KK2 ^ axA));
            uint32_t as_[2][4];
            if (ph2) {
                ldmatrix_x4(as_[0], A2b + (KK2 ^ axA));
                ldmatrix_x4(as_[1], A2b + 2048 + (KK2 ^ axA));
            } else {
                #pragma unroll
                for (int q = 0; q < 4; q++) { as_[0][q] = az[0][q]; as_[1][q] = az[1][q]; }
            }
            #pragma unroll
            for (int fp = 0; fp < 2; fp++) {
                uint32_t b[4];
                ldmatrix_x4(b, Wsb + fp * 2048 + (KK2 ^ axB));
                mma16816(accs[0][2 * fp],     as_[0], b[0], b[1]);
                mma16816(accs[1][2 * fp],     as_[1], b[0], b[1]);
                mma16816(accs[0][2 * fp + 1], as_[0], b[2], b[3]);
                mma16816(accs[1][2 * fp + 1], as_[1], b[2], b[3]);
            }
            #pragma unroll
            for (int fp = 0; fp < 4; fp++) {
                uint32_t b[4];
                ldmatrix_x4(b, Wzb + fp * 2048 + (KK2 ^ axB));
                mma16816(accz[0][2 * fp],     az[0], b[0], b[1]);
                mma16816(accz[1][2 * fp],     az[1], b[0], b[1]);
                mma16816(accz[0][2 * fp + 1], az[0], b[2], b[3]);
                mma16816(accz[1][2 * fp + 1], az[1], b[2], b[3]);
            }
        }
    };

    // ---- prologue: Wz(0), A(0) in flight ------------------------------------
    issueWz(0);
    issueA(0);

    // ---- 8-chunk pipeline ----------------------------------------------------
    // chunk kb: issue Ws(kb) [just-in-time], A(kb+1), Wz(kb+1) [1 chunk ahead];
    //           wait 2 -> retires A(kb), Wz(kb) (hidden) + Ws(kb) (16KB exposed);
    //           sync; compute (R6 body); sync (protect Ws buffer).
#define DO_CHUNK(KB, WSTR)                                   \
    issueWs(KB);                                             \
    if ((KB) < 7) { issueA((KB) + 1); issueWz((KB) + 1); }   \
    CP_WAIT(WSTR);                                           \
    __syncthreads();                                         \
    computeChunk(KB);                                        \
    __syncthreads();

    DO_CHUNK(0, "2")
    DO_CHUNK(1, "2")
    DO_CHUNK(2, "2")
    DO_CHUNK(3, "2")
    DO_CHUNK(4, "2")
    DO_CHUNK(5, "2")
    DO_CHUNK(6, "2")
    DO_CHUNK(7, "0")
#undef DO_CHUNK

    // ---- register-resident epilogue (biases direct from gmem, hoisted) -----
    const int jb = warp_n * 16 + (lane & 3) * 2;
    float2 bz[4][2], bs[2][2];
    #pragma unroll
    for (int g = 0; g < 4; g++)
        #pragma unroll
        for (int jh = 0; jh < 2; jh++)
            bz[g][jh] = *(const float2*)&g_biasz[g * 256 + j0 + jb + jh * 8];
    #pragma unroll
    for (int g = 0; g < 2; g++)
        #pragma unroll
        for (int jh = 0; jh < 2; jh++)
            bs[g][jh] = *(const float2*)&g_biass[g * 256 + j0 + jb + jh * 8];

    #pragma unroll
    for (int mt = 0; mt < 2; mt++) {
        #pragma unroll
        for (int rh = 0; rh < 2; rh++) {
            const int row = m0 + warp_m * 32 + mt * 16 + rh * 8 + (lane >> 2);
            const float mk = mask[row];
            const float* crow = c_in + (size_t)row * H;
            float* orow = out + (size_t)row * H;
            #pragma unroll
            for (int jh = 0; jh < 2; jh++) {
                const int jg = j0 + jb + jh * 8;
                const float2 cold = *(const float2*)(crow + jg);
                float2 hv, cv, s0v, s1v;
                #pragma unroll
                for (int dj = 0; dj < 2; dj++) {
                    const int q = rh * 2 + dj;
                    float z0 = accz[mt][0 + jh][q] + ((dj == 0) ? bz[0][jh].x : bz[0][jh].y);
                    float z1 = accz[mt][2 + jh][q] + ((dj == 0) ? bz[1][jh].x : bz[1][jh].y);
                    float z2 = accz[mt][4 + jh][q] + ((dj == 0) ? bz[2][jh].x : bz[2][jh].y);
                    float z3 = accz[mt][6 + jh][q] + ((dj == 0) ? bz[3][jh].x : bz[3][jh].y);
                    float p0 = accs[mt][0 + jh][q] + ((dj == 0) ? bs[0][jh].x : bs[0][jh].y);
                    float p1 = accs[mt][2 + jh][q] + ((dj == 0) ? bs[1][jh].x : bs[1][jh].y);

                    float gi = fast_sig(z0);
                    float gf = fast_sig(z1);
                    float go = fast_sig(z2);
                    float ch = fast_tanh(z3);
                    float b0 = fast_sig(p0);
                    float b1 = fast_sig(p1);

                    float cc2 = (dj == 0) ? cold.x : cold.y;
                    float ct = (gf * cc2 + gi * ch) * mk;
                    float tc = fast_tanh(ct) * mk;
                    (&hv.x)[dj]  = go * tc;
                    (&cv.x)[dj]  = ct;
                    (&s0v.x)[dj] = b0 * tc;
                    (&s1v.x)[dj] = b1 * tc;
                }
                *(float2*)(orow + jg)                      = hv;
                *(float2*)(orow + (size_t)B_SZ * H + jg)   = cv;
                *(float2*)(orow + 2ull * B_SZ * H + jg)    = s0v;
                *(float2*)(orow + 3ull * B_SZ * H + jg)    = s1v;
            }
        }
    }
}

// ---------------- launch -----------------------------------------------------
extern "C" void kernel_launch(void* const* d_in, const int* in_sizes, int n_in,
                              void* d_out, int out_size) {
    const float* input = (const float*)d_in[0];
    const float* h_m   = (const float*)d_in[1];
    const float* c_m   = (const float*)d_in[2];
    const float* s_m   = (const float*)d_in[3];
    const float* mask  = (const float*)d_in[4];
    const float* w_ih  = (const float*)d_in[5];
    const float* w_hh  = (const float*)d_in[6];
    const float* w_sh  = (const float*)d_in[7];
    const float* b_ih  = (const float*)d_in[8];
    const float* b_hh  = (const float*)d_in[9];
    const float* b_sh  = (const float*)d_in[10];
    const int*   idx   = (const int*)d_in[11];
    float* out = (float*)d_out;

    reorder_kernel<<<770, 1024>>>(w_ih, w_hh, w_sh, b_ih, b_hh, b_sh);
    aconv_kernel<<<dim3(B_SZ * 256 / 8 / 256, 3), 256>>>(input, h_m, s_m, idx);

    static int smem_set = 0;
    if (!smem_set) {
        cudaFuncSetAttribute(lstm_hmma_kernel,
                             cudaFuncAttributeMaxDynamicSharedMemorySize, SMEM_TOTAL);
        smem_set = 1;
    }
    dim3 grid(4, 1024);
    lstm_hmma_kernel<<<grid, 256, SMEM_TOTAL>>>(c_m, mask, out);
}

// round 14
// speedup vs baseline: 1.7431x; 1.7431x over previous
#include <cuda_runtime.h>
#include <cuda_fp16.h>
#include <cstdint>

#define B_SZ 65536
#define H 256

// ---------------- static scratch (no allocation) ----------------------------
// Wz layout: row r = jhi*64 + g*16 + jlo  (j = jhi*16+jlo, g in 0..3), 512 k
// Ws layout: row r = jhi*32 + g*16 + jlo  (g in 0..1), 512 k
__device__ __half g_Wz[1024 * 512];
__device__ __half g_Ws[512 * 512];
__device__ __half g_Ax[(size_t)B_SZ * 256];
__device__ __half g_Ah[(size_t)B_SZ * 256];
__device__ __half g_As[(size_t)B_SZ * 256];
__device__ float  g_biasz[1024];   // [g*256 + j]
__device__ float  g_biass[512];    // [g*256 + j]

// ---------------- prepass kernels (bias merged into reorder) -----------------
__global__ void reorder_kernel(const float* __restrict__ w_ih,
                               const float* __restrict__ w_hh,
                               const float* __restrict__ w_sh,
                               const float* __restrict__ bi,
                               const float* __restrict__ bh,
                               const float* __restrict__ bs) {
    int tid = blockIdx.x * blockDim.x + threadIdx.x;
    if (tid < 1024 * 512) {
        int r = tid >> 9, k = tid & 511;
        int jhi = r >> 6, g = (r >> 4) & 3, jlo = r & 15;
        int j = jhi * 16 + jlo;
        float v = (k < 256) ? w_ih[(g * 256 + j) * 256 + k]
                            : w_hh[(g * 256 + j) * 256 + (k - 256)];
        g_Wz[tid] = __float2half_rn(v);
    } else if (tid < 786432) {
        int t2 = tid - 524288;
        int r = t2 >> 9, k = t2 & 511;
        int jhi = r >> 5, g = (r >> 4) & 1, jlo = r & 15;
        int j = jhi * 16 + jlo;
        float v = (k < 256) ? w_ih[((4 + g) * 256 + j) * 256 + k]
                            : w_sh[(g * 256 + j) * 256 + (k - 256)];
        g_Ws[t2] = __float2half_rn(v);
    } else if (tid < 787456) {
        int t = tid - 786432;
        g_biasz[t] = bi[t] + bh[t];
    } else if (tid < 787968) {
        int t = tid - 787456;
        g_biass[t] = bi[1024 + t] + bs[t];
    }
}

static __device__ __forceinline__ uint32_t h2u(__half2 h) {
    union { __half2 h; uint32_t u; } c; c.h = h; return c.u;
}

__global__ void aconv_kernel(const float* __restrict__ x,
                             const float* __restrict__ hm,
                             const float* __restrict__ s_all,
                             const int* __restrict__ idxp) {
    size_t gid = (size_t)blockIdx.x * blockDim.x + threadIdx.x;
    size_t off = gid * 8;
    const float* src; __half* dst;
    if (blockIdx.y == 0)      { src = x;  dst = g_Ax; }
    else if (blockIdx.y == 1) { src = hm; dst = g_Ah; }
    else { src = s_all + (size_t)(*idxp) * ((size_t)B_SZ * 256); dst = g_As; }
    float4 v0 = *(const float4*)(src + off);
    float4 v1 = *(const float4*)(src + off + 4);
    uint4 p;
    p.x = h2u(__floats2half2_rn(v0.x, v0.y));
    p.y = h2u(__floats2half2_rn(v0.z, v0.w));
    p.z = h2u(__floats2half2_rn(v1.x, v1.y));
    p.w = h2u(__floats2half2_rn(v1.z, v1.w));
    *(uint4*)(dst + off) = p;
}

// ---------------- PTX helpers ------------------------------------------------
static __device__ __forceinline__ uint32_t smem_u32(const void* p) {
    return (uint32_t)__cvta_generic_to_shared(p);
}
static __device__ __forceinline__ void cp16(uint32_t dst, const void* src) {
    asm volatile("cp.async.cg.shared.global [%0], [%1], 16;"
                 :: "r"(dst), "l"(src) : "memory");
}
static __device__ __forceinline__ void cp_commit() {
    asm volatile("cp.async.commit_group;" ::: "memory");
}
static __device__ __forceinline__ void ldmatrix_x4(uint32_t* r, uint32_t addr) {
    asm volatile("ldmatrix.sync.aligned.m8n8.x4.shared.b16 {%0,%1,%2,%3}, [%4];"
                 : "=r"(r[0]), "=r"(r[1]), "=r"(r[2]), "=r"(r[3]) : "r"(addr));
}
static __device__ __forceinline__ void mma16816(float* c, const uint32_t* a,
                                                uint32_t b0, uint32_t b1) {
    asm volatile("mma.sync.aligned.m16n8k16.row.col.f32.f16.f16.f32 "
                 "{%0,%1,%2,%3}, {%4,%5,%6,%7}, {%8,%9}, {%0,%1,%2,%3};"
                 : "+f"(c[0]), "+f"(c[1]), "+f"(c[2]), "+f"(c[3])
                 : "r"(a[0]), "r"(a[1]), "r"(a[2]), "r"(a[3]), "r"(b0), "r"(b1));
}
static __device__ __forceinline__ uint32_t swz(uint32_t o) {
    return o ^ ((o >> 3) & 0x70);
}
static __device__ __forceinline__ float fast_tanh(float x) {
    float r; asm("tanh.approx.f32 %0, %1;" : "=f"(r) : "f"(x)); return r;
}
static __device__ __forceinline__ float fast_sig(float x) {
    return fmaf(0.5f, fast_tanh(0.5f * x), 0.5f);
}

// SMEM map per CTA (bytes)  — EXACT R6 layout:
//  [0,1024) sBz, [1024,1536) sBs
//  [2048, +8K*2)  A1 stages, [18432, +8K*2) A2 stages
//  [34816, +32K)  Wz (single buffer), [67584, +16K) Ws
#define SM_A1(s)  (2048 + (s) * 8192)
#define SM_A2(s)  (18432 + (s) * 8192)
#define SM_WZ     34816
#define SM_WS     67584
#define SMEM_TOTAL 83968

// ---------------- fused HMMA GEMM + LSTM epilogue (R6 verbatim) --------------
__global__ void __launch_bounds__(256, 2)
lstm_hmma_kernel(const float* __restrict__ c_in,
                 const float* __restrict__ mask,
                 float* __restrict__ out)
{
    extern __shared__ char smem[];
    const int tid  = threadIdx.x;
    const int lane = tid & 31;
    const int wid  = tid >> 5;
    const int warp_m = wid & 1;           // 2 warps x 32 rows
    const int warp_n = wid >> 1;          // 4 warps x 16 j
    const int j0 = blockIdx.x * 64;
    const int m0 = blockIdx.y * 64;

    // stage biases into smem in [g][jl] form
    ((float*)smem)[tid] = g_biasz[(tid >> 6) * 256 + j0 + (tid & 63)];
    if (tid < 128) ((float*)(smem + 1024))[tid] = g_biass[(tid >> 6) * 256 + j0 + (tid & 63)];

    float accz[2][8][4], accs[2][4][4];
    #pragma unroll
    for (int mt = 0; mt < 2; mt++) {
        #pragma unroll
        for (int f = 0; f < 8; f++)
            #pragma unroll
            for (int q = 0; q < 4; q++) accz[mt][f][q] = 0.f;
        #pragma unroll
        for (int f = 0; f < 4; f++)
            #pragma unroll
            for (int q = 0; q < 4; q++) accs[mt][f][q] = 0.f;
    }

    // fragment addressing
    const uint32_t rowA  = warp_m * 32 + (lane & 15);
    const uint32_t axA   = ((lane & 7) * 16) ^ ((lane >> 4) * 16);
    const uint32_t offA  = rowA * 128;
    const uint32_t rowB0 = ((lane >> 4) & 1) * 8 + (lane & 7);
    const uint32_t axB   = ((lane & 7) * 16) ^ (((lane >> 3) & 1) * 16);
    const uint32_t offBz = (warp_n * 64 + rowB0) * 128;
    const uint32_t offBs = (warp_n * 32 + rowB0) * 128;
    const uint32_t sbase = smem_u32(smem);

    auto issue_A = [&](int kb) {
        const uint32_t sg = sbase + SM_A1(kb & 1);
        const bool ph1 = (kb < 4);
        const int c0 = (ph1 ? kb : kb - 4) * 64;
        const __half* a1g = ph1 ? g_Ax : g_Ah;
        #pragma unroll
        for (int i = 0; i < 2; i++) {
            int id = tid + i * 256, r = id >> 3, cc = id & 7;
            cp16(sg + swz(r * 128 + cc * 16),
                 a1g + (size_t)(m0 + r) * 256 + c0 + cc * 8);
        }
        if (!ph1) {
            const uint32_t sg2 = sbase + SM_A2(kb & 1);
            #pragma unroll
            for (int i = 0; i < 2; i++) {
                int id = tid + i * 256, r = id >> 3, cc = id & 7;
                cp16(sg2 + swz(r * 128 + cc * 16),
                     g_As + (size_t)(m0 + r) * 256 + c0 + cc * 8);
            }
        }
        cp_commit();
    };
    auto issue_W = [&](int kb) {
        #pragma unroll
        for (int i = 0; i < 8; i++) {
            int id = tid + i * 256, r = id >> 3, cc = id & 7;
            cp16(sbase + SM_WZ + swz(r * 128 + cc * 16),
                 g_Wz + (size_t)(j0 * 4 + r) * 512 + kb * 64 + cc * 8);
        }
        #pragma unroll
        for (int i = 0; i < 4; i++) {
            int id = tid + i * 256, r = id >> 3, cc = id & 7;
            cp16(sbase + SM_WS + swz(r * 128 + cc * 16),
                 g_Ws + (size_t)(j0 * 2 + r) * 512 + kb * 64 + cc * 8);
        }
        cp_commit();
    };

    issue_A(0);

    #pragma unroll 1
    for (int kb = 0; kb < 8; kb++) {
        issue_W(kb);                 // W buffer free: sync at end of prev chunk
        if (kb < 7) issue_A(kb + 1);
        // FIFO: [.., W(kb), A(kb+1)] -> wait 1 completes A(kb) & W(kb)
        if (kb < 7) asm volatile("cp.async.wait_group 1;" ::: "memory");
        else        asm volatile("cp.async.wait_group 0;" ::: "memory");
        __syncthreads();

        const bool ph2 = (kb >= 4);
        const uint32_t A1b = sbase + SM_A1(kb & 1) + offA;
        const uint32_t A2b = sbase + SM_A2(kb & 1) + offA;
        const uint32_t Wzb = sbase + SM_WZ + offBz;
        const uint32_t Wsb = sbase + SM_WS + offBs;

        #pragma unroll
        for (int kk4 = 0; kk4 < 4; kk4++) {
            const uint32_t KK2 = kk4 * 32;
            uint32_t az[2][4];
            ldmatrix_x4(az[0], A1b + (KK2 ^ axA));
            ldmatrix_x4(az[1], A1b + 2048 + (KK2 ^ axA));
            uint32_t as_[2][4];
            if (ph2) {
                ldmatrix_x4(as_[0], A2b + (KK2 ^ axA));
                ldmatrix_x4(as_[1], A2b + 2048 + (KK2 ^ axA));
            } else {
                #pragma unroll
                for (int q = 0; q < 4; q++) { as_[0][q] = az[0][q]; as_[1][q] = az[1][q]; }
            }
            #pragma unroll
            for (int fp = 0; fp < 2; fp++) {
                uint32_t b[4];
                ldmatrix_x4(b, Wsb + fp * 2048 + (KK2 ^ axB));
                mma16816(accs[0][2 * fp],     as_[0], b[0], b[1]);
                mma16816(accs[1][2 * fp],     as_[1], b[0], b[1]);
                mma16816(accs[0][2 * fp + 1], as_[0], b[2], b[3]);
                mma16816(accs[1][2 * fp + 1], as_[1], b[2], b[3]);
            }
            #pragma unroll
            for (int fp = 0; fp < 4; fp++) {
                uint32_t b[4];
                ldmatrix_x4(b, Wzb + fp * 2048 + (KK2 ^ axB));
                mma16816(accz[0][2 * fp],     az[0], b[0], b[1]);
                mma16816(accz[1][2 * fp],     az[1], b[0], b[1]);
                mma16816(accz[0][2 * fp + 1], az[0], b[2], b[3]);
                mma16816(accz[1][2 * fp + 1], az[1], b[2], b[3]);
            }
        }
        __syncthreads();             // all warps done reading W buffer + A stage
    }

    // ---- register-resident epilogue ----------------------------------------
    const float* sBz = (const float*)smem;
    const float* sBs = (const float*)(smem + 1024);
    const int jb = warp_n * 16 + (lane & 3) * 2;

    #pragma unroll
    for (int mt = 0; mt < 2; mt++) {
        #pragma unroll
        for (int rh = 0; rh < 2; rh++) {
            const int row = m0 + warp_m * 32 + mt * 16 + rh * 8 + (lane >> 2);
            const float mk = mask[row];
            const float* crow = c_in + (size_t)row * H;
            float* orow = out + (size_t)row * H;
            #pragma unroll
            for (int jh = 0; jh < 2; jh++) {
                const int jl = jb + jh * 8;
                const int jg = j0 + jl;
                const float2 cold = *(const float2*)(crow + jg);
                float2 hv, cv, s0v, s1v;
                #pragma unroll
                for (int dj = 0; dj < 2; dj++) {
                    const int q = rh * 2 + dj;
                    float z0 = accz[mt][0 + jh][q] + sBz[0 * 64 + jl + dj];
                    float z1 = accz[mt][2 + jh][q] + sBz[1 * 64 + jl + dj];
                    float z2 = accz[mt][4 + jh][q] + sBz[2 * 64 + jl + dj];
                    float z3 = accz[mt][6 + jh][q] + sBz[3 * 64 + jl + dj];
                    float p0 = accs[mt][0 + jh][q] + sBs[0 * 64 + jl + dj];
                    float p1 = accs[mt][2 + jh][q] + sBs[1 * 64 + jl + dj];

                    float gi = fast_sig(z0);
                    float gf = fast_sig(z1);
                    float go = fast_sig(z2);
                    float ch = fast_tanh(z3);
                    float b0 = fast_sig(p0);
                    float b1 = fast_sig(p1);

                    float cc2 = (dj == 0) ? cold.x : cold.y;
                    float ct = (gf * cc2 + gi * ch) * mk;
                    float tc = fast_tanh(ct) * mk;
                    (&hv.x)[dj]  = go * tc;
                    (&cv.x)[dj]  = ct;
                    (&s0v.x)[dj] = b0 * tc;
                    (&s1v.x)[dj] = b1 * tc;
                }
                *(float2*)(orow + jg)                      = hv;
                *(float2*)(orow + (size_t)B_SZ * H + jg)   = cv;
                *(float2*)(orow + 2ull * B_SZ * H + jg)    = s0v;
                *(float2*)(orow + 3ull * B_SZ * H + jg)    = s1v;
            }
        }
    }
}

// ---------------- launch -----------------------------------------------------
extern "C" void kernel_launch(void* const* d_in, const int* in_sizes, int n_in,
                              void* d_out, int out_size) {
    const float* input = (const float*)d_in[0];
    const float* h_m   = (const float*)d_in[1];
    const float* c_m   = (const float*)d_in[2];
    const float* s_m   = (const float*)d_in[3];
    const float* mask  = (const float*)d_in[4];
    const float* w_ih  = (const float*)d_in[5];
    const float* w_hh  = (const float*)d_in[6];
    const float* w_sh  = (const float*)d_in[7];
    const float* b_ih  = (const float*)d_in[8];
    const float* b_hh  = (const float*)d_in[9];
    const float* b_sh  = (const float*)d_in[10];
    const int*   idx   = (const int*)d_in[11];
    float* out = (float*)d_out;

    reorder_kernel<<<770, 1024>>>(w_ih, w_hh, w_sh, b_ih, b_hh, b_sh);
    aconv_kernel<<<dim3(B_SZ * 256 / 8 / 256, 3), 256>>>(input, h_m, s_m, idx);

    static int smem_set = 0;
    if (!smem_set) {
        cudaFuncSetAttribute(lstm_hmma_kernel,
                             cudaFuncAttributeMaxDynamicSharedMemorySize, SMEM_TOTAL);
        smem_set = 1;
    }
    dim3 grid(4, 1024);
    lstm_hmma_kernel<<<grid, 256, SMEM_TOTAL>>>(c_m, mask, out);
}